// round 11
// baseline (speedup 1.0000x reference)
#include <cuda_runtime.h>
#include <cstdint>

// DiscreteAutoregressiveFlow: exact one-hot algebra over Z_257.
// next = (x_t * m[p] + c[p]) mod 257, per-state (m,c) from argmax of W[p]+b.
// Round 11: k_BC rebuilt as a resident cooperative kernel: 1024 blocks
// (SEGLEN=16, UNITS=4, 4 chains/thread -> 55 warps/SM), smem segmaps +
// per-block 258-entry block-map, last-block stitch in SMEM, in-kernel
// replay/scatter. k_A unchanged (~7.1 TB/s effective).

#define V       257
#define B       64
#define L       1024
#define SEGLEN  16
#define UNITS   4                         // segments per block
#define BPB     16                        // blocks per batch
#define SEGBLK  (BPB * B)                 // 1024 blocks
#define REP     8                         // table replication factor
#define NST     258                       // states 0..256 plus 257 = ZERO
#define TOTAL4  ((B * L * V) / 4)         // 4,214,784 uint4
#define TBLK    33                        // table blocks (264 warps >= 258)
#define MIXB    (TOTAL4 / 2048)           // 2058 blocks per role (exact)
#define DEADE   (66048u << 9)             // dead: m=0, c=66048 -> slot 0

// Slot convention: slot 0 = ZERO/dead; slot s in [1,513] = state (s-1) mod 257.
// Step: z = x*m + c (alive z <= 65792); z mod 257 == (z&255)-(z>>8) (mod 257);
// w = lo - hi + 258 in [1,513] alive, 0 for the dead trap (hi=258). Branch-free.

__device__ unsigned g_tab[NST];                          // m | c<<9 (or DEADE)
__device__ __align__(16) int   g_xidx[B * L];
__device__ __align__(16) short g_bmap[B * BPB * NST];    // block-level maps
__device__ int g_entry[B * BPB];                         // entry state per block
__device__ int g_done[B];                                // zero-init; self-reset
__device__ volatile int g_go[B];                         // zero-init; self-reset
__device__ int g_fin[B];                                 // zero-init; self-reset

__device__ __forceinline__ int slot2state(int s) {       // [0,513] -> 0..257
    return (s == 0) ? V : ((s <= V) ? s - 1 : s - (V + 1));
}

// ---------------------------------------------------------------------------
// K_A: three block roles; read stream (extract) and write stream (zero-fill)
// share the HBM pipe; tables computed by the first 33 blocks. (Unchanged.)
// ---------------------------------------------------------------------------
__global__ void __launch_bounds__(256) k_A(const float* __restrict__ W,
                                           const float* __restrict__ bb,
                                           const int*   __restrict__ inv_table,
                                           const uint4* __restrict__ x,
                                           uint4*       __restrict__ out) {
    int bid = blockIdx.x;
    int tid = threadIdx.x;

    if (bid < TBLK) {
        int p    = bid * 8 + (tid >> 5);
        int lane = tid & 31;
        if (p >= NST) return;
        const float* wrow = (p < V) ? (W + (size_t)p * (2 * V)) : nullptr;
        int bestj[2];
        #pragma unroll
        for (int h = 0; h < 2; h++) {
            float bv = -3.402823466e38f;
            int   bj = 0;
            for (int j = lane; j < V; j += 32) {
                int   col = h * V + j;
                float v   = bb[col] + (wrow ? wrow[col] : 0.0f);
                if (v > bv) { bv = v; bj = j; }     // first-max == jnp.argmax
            }
            #pragma unroll
            for (int off = 16; off; off >>= 1) {
                float ov = __shfl_down_sync(0xffffffffu, bv, off);
                int   oj = __shfl_down_sync(0xffffffffu, bj, off);
                if (ov > bv || (ov == bv && oj < bj)) { bv = ov; bj = oj; }
            }
            bestj[h] = bj;
        }
        if (lane == 0) {
            int l = bestj[0], s = bestj[1];
            int m = inv_table[s];                 // 0 iff s==0
            unsigned e = DEADE;
            if (m != 0) {
                int c = (V - (l * m) % V) % V;    // (-l*m) mod V
                e = (unsigned)m | ((unsigned)c << 9);
            }
            g_tab[p] = e;
        }
        return;
    }

    int mm   = bid - TBLK;
    int unit = mm >> 1;
    int base = unit * 2048 + tid;

    if (mm & 1) {
        uint4 z = make_uint4(0u, 0u, 0u, 0u);
        #pragma unroll
        for (int k = 0; k < 8; k++) out[base + k * 256] = z;
        return;
    }

    // extract: 8 coalesced uint4 loads front-batched (MLP_p1 = 8)
    uint4 v[8];
    #pragma unroll
    for (int k = 0; k < 8; k++) v[k] = x[base + k * 256];
    #pragma unroll
    for (int k = 0; k < 8; k++) {
        if (v[k].x | v[k].y | v[k].z | v[k].w) {
            unsigned a[4] = { v[k].x, v[k].y, v[k].z, v[k].w };
            int eb = (base + k * 256) * 4;
            #pragma unroll
            for (int j = 0; j < 4; j++) {
                if (a[j] != 0u) {
                    int idx = eb + j;
                    int row = idx / V;
                    g_xidx[row] = idx - row * V;
                }
            }
        }
    }
}

// ---------------------------------------------------------------------------
// K_BC: cooperative. 16 blocks per batch, all resident (27KB smem, <=36 regs,
// grid 1024 <= 7 blocks/SM * 148). Phases per block:
//   1. segmap: 4 chains/thread x 16 steps, segmaps kept in SMEM.
//   2. compose own 4 segmaps -> 258-entry block-map; publish (516B).
//   3. last-arriving block: stitch 16 block-maps IN SMEM, publish entries+go.
//   4. all blocks: read entry, walk own segmaps for per-unit entries,
//      replay 16 steps/unit, scatter 1.0f into the pre-zeroed output.
// ---------------------------------------------------------------------------
__global__ void __launch_bounds__(256, 7) k_BC(float* __restrict__ out) {
    __shared__ unsigned tabR[514 * REP];                 // 16448 B
    __shared__ __align__(16) short segmapS[UNITS * NST]; // 2064 B
    __shared__ __align__(16) short bmapsS[BPB * NST];    // 8256 B (stitch only)
    __shared__ __align__(16) int   sxs[SEGLEN * UNITS];  // 256 B, [t*4+u]
    __shared__ int entryU[UNITS];
    __shared__ int isLast;

    int bid = blockIdx.x;
    int tid = threadIdx.x;
    int b   = bid / BPB;
    int blk = bid % BPB;

    for (int i = tid; i < 514 * REP; i += 256)
        tabR[i] = g_tab[slot2state(i >> 3)];             // REP = 8
    if (tid < SEGLEN * UNITS) {
        int u = tid & 3, t = tid >> 2;
        sxs[t * 4 + u] = g_xidx[b * L + (blk * UNITS + u) * SEGLEN + t];
    }
    __syncthreads();

    // ---- phase 1: segment maps (4 chains/thread + extra on t<8) ----
    int rep = tid & (REP - 1);
    int xst = 256 + (tid & 1);          // extra-chain state (threads 0..7)
    int xun = (tid >> 1) & 3;           // extra-chain unit
    bool extra = (tid < 8);

    int slot[5];
    #pragma unroll
    for (int j = 0; j < 4; j++) slot[j] = tid + 1;       // state tid -> slot tid+1
    slot[4] = (xst == V) ? 0 : xst + 1;

    #pragma unroll
    for (int t = 0; t < SEGLEN; t++) {
        uint4 xv = *(const uint4*)&sxs[t * 4];           // broadcast LDS.128
        unsigned xs[4] = { xv.x, xv.y, xv.z, xv.w };
        #pragma unroll
        for (int j = 0; j < 4; j++) {
            unsigned e = tabR[slot[j] * REP + rep];
            unsigned z = xs[j] * (e & 511u) + (e >> 9);
            slot[j] = (int)(z & 255u) - (int)(z >> 8) + 258;
        }
        if (extra) {
            unsigned e = tabR[slot[4] * REP + rep];
            unsigned z = (unsigned)sxs[t * 4 + xun] * (e & 511u) + (e >> 9);
            slot[4] = (int)(z & 255u) - (int)(z >> 8) + 258;
        }
    }

    #pragma unroll
    for (int j = 0; j < 4; j++)
        segmapS[j * NST + tid] = (short)slot2state(slot[j]);
    if (extra)
        segmapS[xun * NST + xst] = (short)slot2state(slot[4]);
    __syncthreads();

    // ---- phase 2: compose own segmaps -> block-map, publish ----
    {
        int cur = segmapS[tid];
        #pragma unroll
        for (int u = 1; u < UNITS; u++) cur = segmapS[u * NST + cur];
        g_bmap[(size_t)(b * BPB + blk) * NST + tid] = (short)cur;
        if (tid < 2) {                                   // states 256, 257
            int c2 = segmapS[256 + tid];
            #pragma unroll
            for (int u = 1; u < UNITS; u++) c2 = segmapS[u * NST + c2];
            g_bmap[(size_t)(b * BPB + blk) * NST + 256 + tid] = (short)c2;
        }
    }
    __threadfence();
    __syncthreads();
    if (tid == 0) isLast = (atomicAdd(&g_done[b], 1) == BPB - 1);
    __syncthreads();

    // ---- phase 3: last block stitches the batch in SMEM ----
    if (isLast) {
        __threadfence();                                 // acquire peers' bmaps
        const uint4* src = (const uint4*)(g_bmap + (size_t)b * BPB * NST);
        uint4* dst = (uint4*)bmapsS;
        #pragma unroll
        for (int k = 0; k < 2; k++) dst[tid + 256 * k] = src[tid + 256 * k];
        if (tid < 4) dst[512 + tid] = src[512 + tid];    // 516 total
        __syncthreads();
        if (tid == 0) {
            int st = V;  // ZERO
            #pragma unroll
            for (int k = 0; k < BPB; k++) {
                g_entry[b * BPB + k] = st;
                st = bmapsS[k * NST + st];
            }
            __threadfence();
            g_go[b] = 1;                                 // release
        }
    }

    // ---- phase 4: all blocks wait, then replay + scatter ----
    if (tid == 0) {
        while (g_go[b] == 0) __nanosleep(64);
    }
    __syncthreads();
    __threadfence();                                     // acquire entries

    if (tid == 0) {
        int st = g_entry[b * BPB + blk];
        #pragma unroll
        for (int u = 0; u < UNITS; u++) {
            entryU[u] = st;
            st = segmapS[u * NST + st];
        }
    }
    __syncthreads();

    {
        int w = tid >> 5, lane = tid & 31;
        if (w < UNITS && lane == 0) {
            int ent = entryU[w];
            int sl  = (ent == V) ? 0 : ent + 1;
            float* orow = out + (size_t)(b * L + (blk * UNITS + w) * SEGLEN) * V;
            #pragma unroll
            for (int t = 0; t < SEGLEN; t++) {
                unsigned e = tabR[sl * REP];
                unsigned z = (unsigned)sxs[t * 4 + w] * (e & 511u) + (e >> 9);
                sl = (int)(z & 255u) - (int)(z >> 8) + 258;
                if (sl != 0) {
                    int oi = (sl <= V) ? sl - 1 : sl - (V + 1);
                    orow[(size_t)t * V + oi] = 1.0f;
                }
            }
        }
    }
    __syncthreads();

    if (tid == 0) {                                      // self-reset for replay
        if (atomicAdd(&g_fin[b], 1) == BPB - 1) {
            g_done[b] = 0;
            g_fin[b]  = 0;
            g_go[b]   = 0;
            __threadfence();
        }
    }
}

// ---------------------------------------------------------------------------
extern "C" void kernel_launch(void* const* d_in, const int* in_sizes, int n_in,
                              void* d_out, int out_size) {
    const float* x   = (const float*)d_in[0];   // [B, L, V] f32
    const float* W   = (const float*)d_in[1];   // [V, 2V]   f32
    const float* bb  = (const float*)d_in[2];   // [2V]      f32
    const int*   inv = (const int*)  d_in[3];   // [V]       i32

    k_A<<<TBLK + 2 * MIXB, 256>>>(W, bb, inv, (const uint4*)x, (uint4*)d_out);
    k_BC<<<SEGBLK, 256>>>((float*)d_out);
}